// round 1
// baseline (speedup 1.0000x reference)
#include <cuda_runtime.h>

// ---------------- problem constants ----------------
#define KS    11
#define RAD   5          // KS/2
#define H2    10         // double halo (mu halo + sigma halo)
#define TX    32         // output tile
#define TY    32
#define IW    52         // input tile extent  (TX + 2*H2)
#define IWP   56         // padded width of input tile (16B-aligned rows, pad cols zeroed)
#define MW    42         // mid extent (TX + 2*RAD)
#define MWP   44         // padded mid width
#define IMG_H 1024
#define IMG_W 1024
#define NBAT  16
#define NPIX  16777216.0 // 16*1024*1024

// smem layout (floats)
#define OFF_IMG1  0
#define OFF_IMG2  (IW*IWP)
#define OFF_H1    (2*IW*IWP)
#define OFF_H2    (2*IW*IWP + IW*MWP)
#define OFF_MU1   (2*IW*IWP + 2*IW*MWP)
#define OFF_MU2   (OFF_MU1 + MW*MWP)
#define OFF_P1    (OFF_MU1 + 2*MW*MWP)
#define OFF_P2    (OFF_MU1 + 3*MW*MWP)
#define OFF_P12   (OFF_MU1 + 4*MW*MWP)
#define OFF_Q1    (OFF_MU1 + 5*MW*MWP)
#define OFF_Q2    (OFF_Q1 + MW*TX)
#define OFF_Q12   (OFF_Q1 + 2*MW*TX)
#define SMEM_FLOATS (OFF_Q1 + 3*MW*TX)
#define SMEM_BYTES  (SMEM_FLOATS * 4)

// ---------------- device globals ----------------
__device__ float        g_g1d[16];
__device__ unsigned int g_minkey;
__device__ unsigned int g_maxkey;
__device__ double       g_accum;

// orderable-uint transform for float atomics (monotonic increasing)
__device__ __forceinline__ unsigned int f2key(float f) {
    unsigned int u = __float_as_uint(f);
    return (u & 0x80000000u) ? ~u : (u | 0x80000000u);
}
__device__ __forceinline__ float key2f(unsigned int k) {
    unsigned int u = (k & 0x80000000u) ? (k & 0x7fffffffu) : ~k;
    return __uint_as_float(u);
}

// ---------------- kernel 1: init (reset accumulators, extract 1D gaussian) ----------------
__global__ void init_kernel(const float* __restrict__ k2d) {
    int t = threadIdx.x;
    if (t == 0) {
        g_accum  = 0.0;
        g_minkey = 0xFFFFFFFFu;
        g_maxkey = 0u;
    }
    if (t < KS) {
        // k2d = outer(g,g), rows sum to g[i] * sum(g) ~= g[i]
        float s = 0.f;
        #pragma unroll
        for (int j = 0; j < KS; j++) s += k2d[t * KS + j];
        g_g1d[t] = s;
    }
}

// ---------------- kernel 2: global min/max over both images ----------------
__global__ __launch_bounds__(256) void minmax_kernel(
    const float4* __restrict__ a, const float4* __restrict__ b, int n4)
{
    float mn = 1e30f, mx = -1e30f;
    int stride = gridDim.x * blockDim.x;
    for (int i = blockIdx.x * blockDim.x + threadIdx.x; i < n4; i += stride) {
        float4 v = a[i];
        float4 u = b[i];
        mn = fminf(mn, fminf(fminf(v.x, v.y), fminf(v.z, v.w)));
        mx = fmaxf(mx, fmaxf(fmaxf(v.x, v.y), fmaxf(v.z, v.w)));
        mn = fminf(mn, fminf(fminf(u.x, u.y), fminf(u.z, u.w)));
        mx = fmaxf(mx, fmaxf(fmaxf(u.x, u.y), fmaxf(u.z, u.w)));
    }
    #pragma unroll
    for (int o = 16; o; o >>= 1) {
        mn = fminf(mn, __shfl_xor_sync(0xFFFFFFFFu, mn, o));
        mx = fmaxf(mx, __shfl_xor_sync(0xFFFFFFFFu, mx, o));
    }
    __shared__ float smn[8], smx[8];
    int tid = threadIdx.x;
    if ((tid & 31) == 0) { smn[tid >> 5] = mn; smx[tid >> 5] = mx; }
    __syncthreads();
    if (tid == 0) {
        #pragma unroll
        for (int w = 1; w < 8; w++) { mn = fminf(mn, smn[w]); mx = fmaxf(mx, smx[w]); }
        atomicMin(&g_minkey, f2key(mn));
        atomicMax(&g_maxkey, f2key(mx));
    }
}

// ---------------- kernel 3: fused SSIM over 32x32 output tiles ----------------
__global__ __launch_bounds__(256, 2) void ssim_kernel(
    const float* __restrict__ img1, const float* __restrict__ img2)
{
    extern __shared__ float sm[];
    float* simg1 = sm + OFF_IMG1;
    float* simg2 = sm + OFF_IMG2;
    float* sh1   = sm + OFF_H1;
    float* sh2   = sm + OFF_H2;
    float* smu1  = sm + OFF_MU1;
    float* smu2  = sm + OFF_MU2;
    float* sp1   = sm + OFF_P1;
    float* sp2   = sm + OFF_P2;
    float* sp12  = sm + OFF_P12;
    float* sq1   = sm + OFF_Q1;
    float* sq2   = sm + OFF_Q2;
    float* sq12  = sm + OFF_Q12;

    const int tid = threadIdx.x;
    const int ox = blockIdx.x * TX;
    const int oy = blockIdx.y * TY;
    const float* i1 = img1 + (size_t)blockIdx.z * (IMG_H * IMG_W);
    const float* i2 = img2 + (size_t)blockIdx.z * (IMG_H * IMG_W);

    float g[KS];
    #pragma unroll
    for (int k = 0; k < KS; k++) g[k] = g_g1d[k];

    const float vr = key2f(g_maxkey) - key2f(g_minkey) + 1e-5f;
    float C1 = 0.01f * vr; C1 *= C1;
    float C2 = 0.03f * vr; C2 *= C2;

    // ---- load input tiles (with zero padding for OOB and pad cols) ----
    for (int i = tid; i < IW * IWP; i += 256) {
        int y = i / IWP, x = i % IWP;
        int gy = oy - H2 + y, gx = ox - H2 + x;
        bool ok = (x < IW) && (gy >= 0) && (gy < IMG_H) && (gx >= 0) && (gx < IMG_W);
        int gidx = gy * IMG_W + gx;
        simg1[i] = ok ? i1[gidx] : 0.f;
        simg2[i] = ok ? i2[gidx] : 0.f;
    }
    __syncthreads();

    // ---- stage 1: horizontal conv of img1/img2 -> h1,h2  (52 rows x 42 cols) ----
    // units: 52 rows x 11 col-groups of 4 (outputs beyond col 41 land in pad, never read)
    for (int u = tid; u < IW * 11; u += 256) {
        int y = u / 11, x0 = (u % 11) * 4;
        const float* r1 = simg1 + y * IWP + x0;
        const float* r2 = simg2 + y * IWP + x0;
        float w1[14], w2[14];
        #pragma unroll
        for (int j = 0; j < 14; j++) { w1[j] = r1[j]; w2[j] = r2[j]; } // x0+13 <= 53 < IWP
        #pragma unroll
        for (int xx = 0; xx < 4; xx++) {
            float a = 0.f, b = 0.f;
            #pragma unroll
            for (int k = 0; k < KS; k++) {
                a = fmaf(g[k], w1[xx + k], a);
                b = fmaf(g[k], w2[xx + k], b);
            }
            sh1[y * MWP + x0 + xx] = a;
            sh2[y * MWP + x0 + xx] = b;
        }
    }
    __syncthreads();

    // ---- stage 2: vertical conv of h1,h2 -> mu1,mu2  (42 x 42) ----
    // units: 11 row-groups of 4 x 42 cols
    for (int u = tid; u < 11 * MW; u += 256) {
        int x = u % MW, y0 = (u / MW) * 4;
        float w1[14], w2[14];
        #pragma unroll
        for (int j = 0; j < 14; j++) {
            int yy = y0 + j;
            bool ok = (yy < IW);
            w1[j] = ok ? sh1[yy * MWP + x] : 0.f;
            w2[j] = ok ? sh2[yy * MWP + x] : 0.f;
        }
        #pragma unroll
        for (int yy = 0; yy < 4; yy++) {
            float a = 0.f, b = 0.f;
            #pragma unroll
            for (int k = 0; k < KS; k++) {
                a = fmaf(g[k], w1[yy + k], a);
                b = fmaf(g[k], w2[yy + k], b);
            }
            if (y0 + yy < MW) {
                smu1[(y0 + yy) * MWP + x] = a;
                smu2[(y0 + yy) * MWP + x] = b;
            }
        }
    }
    __syncthreads();

    // ---- stage 3: deviations and products (42 x 42) ----
    for (int i = tid; i < MW * MW; i += 256) {
        int y = i / MW, x = i % MW;
        int mi = y * MWP + x;
        float d1 = simg1[(y + RAD) * IWP + (x + RAD)] - smu1[mi];
        float d2 = simg2[(y + RAD) * IWP + (x + RAD)] - smu2[mi];
        sp1[mi]  = d1 * d1;
        sp2[mi]  = d2 * d2;
        sp12[mi] = d1 * d2;
    }
    __syncthreads();

    // ---- stage 4: horizontal conv of products -> q1,q2,q12  (42 x 32) ----
    for (int u = tid; u < MW * 8; u += 256) {
        int y = u / 8, x0 = (u % 8) * 4;
        const float* p1 = sp1 + y * MWP + x0;
        const float* p2 = sp2 + y * MWP + x0;
        const float* p3 = sp12 + y * MWP + x0;
        float w1[14], w2[14], w3[14];
        #pragma unroll
        for (int j = 0; j < 14; j++) { w1[j] = p1[j]; w2[j] = p2[j]; w3[j] = p3[j]; }
        #pragma unroll
        for (int xx = 0; xx < 4; xx++) {
            float a = 0.f, b = 0.f, c = 0.f;
            #pragma unroll
            for (int k = 0; k < KS; k++) {
                a = fmaf(g[k], w1[xx + k], a);
                b = fmaf(g[k], w2[xx + k], b);
                c = fmaf(g[k], w3[xx + k], c);
            }
            sq1[y * TX + x0 + xx]  = a;
            sq2[y * TX + x0 + xx]  = b;
            sq12[y * TX + x0 + xx] = c;
        }
    }
    __syncthreads();

    // ---- stage 5: vertical conv of q -> sigma terms, final SSIM math (32 x 32) ----
    float lsum = 0.f;
    {
        int u = tid;                    // exactly 256 units: 8 row-groups x 32 cols
        int x = u % TX, y0 = (u / TX) * 4;
        float w1[14], w2[14], w3[14];
        #pragma unroll
        for (int j = 0; j < 14; j++) {  // y0+13 <= 41 < 42: no guard
            w1[j] = sq1[(y0 + j) * TX + x];
            w2[j] = sq2[(y0 + j) * TX + x];
            w3[j] = sq12[(y0 + j) * TX + x];
        }
        #pragma unroll
        for (int yy = 0; yy < 4; yy++) {
            float a = 0.f, b = 0.f, c = 0.f;
            #pragma unroll
            for (int k = 0; k < KS; k++) {
                a = fmaf(g[k], w1[yy + k], a);
                b = fmaf(g[k], w2[yy + k], b);
                c = fmaf(g[k], w3[yy + k], c);
            }
            int py = y0 + yy;
            float m1 = smu1[(py + RAD) * MWP + (x + RAD)];
            float m2 = smu2[(py + RAD) * MWP + (x + RAD)];
            // structure = (2*(c+1)+C2) / ((a+1)+(b+1)+C2)
            float snum = 2.f * c + 2.f + C2;
            float sden = a + b + 2.f + C2;
            // brightness = ((2*(m1*m2+1))^2 + C1) / (((m1^2+1)+(m2^2+1))^2 + C1)
            float m12  = m1 * m2 + 1.f;
            float t    = 2.f * m12;
            float msum = m1 * m1 + m2 * m2 + 2.f;
            float bnum = t * t + C1;
            float bden = msum * msum + C1;
            lsum += __fdividef(snum * bnum, sden * bden);
        }
    }

    // ---- block reduction + global accumulate ----
    #pragma unroll
    for (int o = 16; o; o >>= 1) lsum += __shfl_xor_sync(0xFFFFFFFFu, lsum, o);
    __shared__ float red[8];
    if ((tid & 31) == 0) red[tid >> 5] = lsum;
    __syncthreads();
    if (tid == 0) {
        float v = red[0];
        #pragma unroll
        for (int w = 1; w < 8; w++) v += red[w];
        atomicAdd(&g_accum, (double)v);
    }
}

// ---------------- kernel 4: finalize ----------------
__global__ void finalize_kernel(float* __restrict__ out) {
    out[0] = (float)(1.0 - g_accum * (1.0 / NPIX));
}

// ---------------- launch ----------------
extern "C" void kernel_launch(void* const* d_in, const int* in_sizes, int n_in,
                              void* d_out, int out_size) {
    const float* img1 = (const float*)d_in[0];
    const float* img2 = (const float*)d_in[1];
    const float* k2d  = (const float*)d_in[2];
    float* out = (float*)d_out;

    init_kernel<<<1, 32>>>(k2d);

    int n4 = (NBAT * IMG_H * IMG_W) / 4;
    minmax_kernel<<<2048, 256>>>((const float4*)img1, (const float4*)img2, n4);

    cudaFuncSetAttribute(ssim_kernel, cudaFuncAttributeMaxDynamicSharedMemorySize, SMEM_BYTES);
    dim3 grid(IMG_W / TX, IMG_H / TY, NBAT);
    ssim_kernel<<<grid, 256, SMEM_BYTES>>>(img1, img2);

    finalize_kernel<<<1, 1>>>(out);
}

// round 2
// speedup vs baseline: 1.3125x; 1.3125x over previous
#include <cuda_runtime.h>

// ---------------- problem constants ----------------
#define KS    11
#define RAD   5
#define H2    10
#define TX    32
#define TY    32
#define IW    52          // TX + 2*H2
#define IWP   56          // padded input tile width (float2 units)
#define MW    42          // TX + 2*RAD
#define MWP   44          // padded mid width
#define IMG_H 1024
#define IMG_W 1024
#define NBAT  16
#define NPIX  16777216.0

// smem layout in floats
#define F_AB   0                        // float2[IW][IWP]           5824 f
#define F_H    (F_AB + 2*IW*IWP)        // float2[IW][MWP]  (reused: P) 4576 f
#define F_MU   (F_H + 2*IW*MWP)         // float2[MW][MWP]           3696 f
#define F_P12  (F_MU + 2*MW*MWP)        // float [MW][MWP]           1848 f
#define SMEM_FLOATS (F_P12 + MW*MWP)    // 15944 floats = 63776 B
#define SMEM_BYTES  (SMEM_FLOATS * 4)

typedef unsigned long long u64;

// ---------------- f32x2 helpers ----------------
__device__ __forceinline__ u64 pack2(float lo, float hi) {
    u64 r; asm("mov.b64 %0, {%1, %2};" : "=l"(r) : "f"(lo), "f"(hi)); return r;
}
__device__ __forceinline__ void unpack2(u64 v, float& lo, float& hi) {
    asm("mov.b64 {%0, %1}, %2;" : "=f"(lo), "=f"(hi) : "l"(v));
}
__device__ __forceinline__ u64 fma2(u64 a, u64 b, u64 c) {
    u64 d; asm("fma.rn.f32x2 %0, %1, %2, %3;" : "=l"(d) : "l"(a), "l"(b), "l"(c)); return d;
}
__device__ __forceinline__ u64 mul2(u64 a, u64 b) {
    u64 d; asm("mul.rn.f32x2 %0, %1, %2;" : "=l"(d) : "l"(a), "l"(b)); return d;
}

// ---------------- device globals ----------------
__device__ float        g_g1d[16];
__device__ unsigned int g_minkey;
__device__ unsigned int g_maxkey;
__device__ double       g_accum;

__device__ __forceinline__ unsigned int f2key(float f) {
    unsigned int u = __float_as_uint(f);
    return (u & 0x80000000u) ? ~u : (u | 0x80000000u);
}
__device__ __forceinline__ float key2f(unsigned int k) {
    unsigned int u = (k & 0x80000000u) ? (k & 0x7fffffffu) : ~k;
    return __uint_as_float(u);
}

// ---------------- kernel 1: init ----------------
__global__ void init_kernel(const float* __restrict__ k2d) {
    int t = threadIdx.x;
    if (t == 0) { g_accum = 0.0; g_minkey = 0xFFFFFFFFu; g_maxkey = 0u; }
    if (t < KS) {
        float s = 0.f;
        #pragma unroll
        for (int j = 0; j < KS; j++) s += k2d[t * KS + j];
        g_g1d[t] = s;
    }
}

// ---------------- kernel 2: global min/max ----------------
__global__ __launch_bounds__(256) void minmax_kernel(
    const float4* __restrict__ a, const float4* __restrict__ b, int n4)
{
    float mn = 1e30f, mx = -1e30f;
    int stride = gridDim.x * blockDim.x;
    for (int i = blockIdx.x * blockDim.x + threadIdx.x; i < n4; i += stride) {
        float4 v = a[i];
        float4 u = b[i];
        mn = fminf(mn, fminf(fminf(v.x, v.y), fminf(v.z, v.w)));
        mx = fmaxf(mx, fmaxf(fmaxf(v.x, v.y), fmaxf(v.z, v.w)));
        mn = fminf(mn, fminf(fminf(u.x, u.y), fminf(u.z, u.w)));
        mx = fmaxf(mx, fmaxf(fmaxf(u.x, u.y), fmaxf(u.z, u.w)));
    }
    #pragma unroll
    for (int o = 16; o; o >>= 1) {
        mn = fminf(mn, __shfl_xor_sync(0xFFFFFFFFu, mn, o));
        mx = fmaxf(mx, __shfl_xor_sync(0xFFFFFFFFu, mx, o));
    }
    __shared__ float smn[8], smx[8];
    int tid = threadIdx.x;
    if ((tid & 31) == 0) { smn[tid >> 5] = mn; smx[tid >> 5] = mx; }
    __syncthreads();
    if (tid == 0) {
        #pragma unroll
        for (int w = 1; w < 8; w++) { mn = fminf(mn, smn[w]); mx = fmaxf(mx, smx[w]); }
        atomicMin(&g_minkey, f2key(mn));
        atomicMax(&g_maxkey, f2key(mx));
    }
}

// ---------------- kernel 3: fused SSIM, f32x2-packed ----------------
__global__ __launch_bounds__(256, 3) void ssim_kernel(
    const float* __restrict__ img1, const float* __restrict__ img2)
{
    extern __shared__ float sm[];
    u64*   AB  = (u64*)(sm + F_AB);            // interleaved {img1,img2} [IW][IWP]
    u64*   Hh  = (u64*)(sm + F_H);             // horiz conv pair [IW][MWP]
    u64*   MU  = (u64*)(sm + F_MU);            // {mu1,mu2} [MW][MWP]
    float* P12 = sm + F_P12;                   // d1*d2 [MW][MWP]
    u64*   Pp  = Hh;                           // alias: {d1^2,d2^2} [MW][MWP]
    u64*   Q   = (u64*)(sm + F_AB);            // alias: {q1,q2} [MW][TX]
    float* Q12 = sm + F_AB + 2*MW*TX;          // alias: q12 [MW][TX]
    u64*   SIG = (u64*)(sm + F_H);             // alias: {sigA,sigB} [TX][TX]
    u64*   CCp = (u64*)(sm + F_H + 2*TX*TX);   // alias: c col-pairs [TX][TX/2]
    float* CC  = (float*)CCp;                  // same region as scalar [TX][TX]

    const int tid = threadIdx.x;
    const int ox = blockIdx.x * TX;
    const int oy = blockIdx.y * TY;
    const float* i1 = img1 + (size_t)blockIdx.z * (IMG_H * IMG_W);
    const float* i2 = img2 + (size_t)blockIdx.z * (IMG_H * IMG_W);

    float g[KS];
    u64 gg[KS];
    #pragma unroll
    for (int k = 0; k < KS; k++) { g[k] = g_g1d[k]; gg[k] = pack2(g[k], g[k]); }

    const float vr = key2f(g_maxkey) - key2f(g_minkey) + 1e-5f;
    float C1 = 0.01f * vr; C1 *= C1;
    float C2 = 0.03f * vr; C2 *= C2;

    // ---- load: interleave {img1,img2}, float2 global loads (per-pair guards valid:
    //      ox-10 is even, so OOB boundaries fall on pair boundaries) ----
    for (int u = tid; u < IW * (IWP / 2); u += 256) {
        int y = u / (IWP / 2), xp = u % (IWP / 2);
        int c = 2 * xp;
        int gy = oy - H2 + y, gx = ox - H2 + c;
        bool ok = (c < IW) && (gy >= 0) && (gy < IMG_H) && (gx >= 0) && (gx + 1 < IMG_W);
        float2 va = make_float2(0.f, 0.f), vb = va;
        if (ok) {
            va = *(const float2*)(i1 + gy * IMG_W + gx);
            vb = *(const float2*)(i2 + gy * IMG_W + gx);
        }
        AB[y * IWP + c]     = pack2(va.x, vb.x);
        AB[y * IWP + c + 1] = pack2(va.y, vb.y);
    }
    __syncthreads();

    // ---- stage 1: horizontal conv (both images at once) -> Hh [52 x 42] ----
    for (int u = tid; u < IW * 11; u += 256) {       // 572 units
        int y = u / 11, x0 = (u % 11) * 4;
        const u64* r = AB + y * IWP + x0;
        u64 w[14];
        #pragma unroll
        for (int j = 0; j < 14; j++) w[j] = r[j];
        u64 acc[4] = {0ull, 0ull, 0ull, 0ull};
        #pragma unroll
        for (int k = 0; k < KS; k++) {
            #pragma unroll
            for (int xx = 0; xx < 4; xx++) acc[xx] = fma2(gg[k], w[xx + k], acc[xx]);
        }
        #pragma unroll
        for (int xx = 0; xx < 4; xx++) Hh[y * MWP + x0 + xx] = acc[xx];
    }
    __syncthreads();

    // ---- stage 2: vertical conv -> MU [42 x 42] ----
    for (int u = tid; u < 11 * MW; u += 256) {       // 462 units
        int x = u % MW, y0 = (u / MW) * 4;
        u64 w[14];
        #pragma unroll
        for (int j = 0; j < 14; j++) {
            int yy = y0 + j;
            w[j] = (yy < IW) ? Hh[yy * MWP + x] : 0ull;
        }
        u64 acc[4] = {0ull, 0ull, 0ull, 0ull};
        #pragma unroll
        for (int k = 0; k < KS; k++) {
            #pragma unroll
            for (int yy = 0; yy < 4; yy++) acc[yy] = fma2(gg[k], w[yy + k], acc[yy]);
        }
        #pragma unroll
        for (int yy = 0; yy < 4; yy++)
            if (y0 + yy < MW) MU[(y0 + yy) * MWP + x] = acc[yy];
    }
    __syncthreads();

    // ---- stage 3: deviations + products  (writes Pp aliasing Hh, and P12) ----
    for (int i = tid; i < MW * MW; i += 256) {
        int y = i / MW, x = i % MW;
        u64 ab = AB[(y + RAD) * IWP + (x + RAD)];
        u64 mu = MU[y * MWP + x];
        float a1, a2, m1, m2;
        unpack2(ab, a1, a2);
        unpack2(mu, m1, m2);
        float d1 = a1 - m1, d2 = a2 - m2;
        u64 dd = pack2(d1, d2);
        Pp[y * MWP + x] = mul2(dd, dd);    // {d1^2, d2^2}
        P12[y * MWP + x] = d1 * d2;
    }
    __syncthreads();

    // ---- stage 4: horizontal conv of products -> Q {q1,q2} and Q12  [42 x 32] ----
    for (int u = tid; u < 504; u += 256) {
        if (u < 336) {                                // pair stream: 42 rows x 8 groups
            int y = u / 8, x0 = (u % 8) * 4;
            const u64* r = Pp + y * MWP + x0;
            u64 w[14];
            #pragma unroll
            for (int j = 0; j < 14; j++) w[j] = r[j];
            u64 acc[4] = {0ull, 0ull, 0ull, 0ull};
            #pragma unroll
            for (int k = 0; k < KS; k++) {
                #pragma unroll
                for (int xx = 0; xx < 4; xx++) acc[xx] = fma2(gg[k], w[xx + k], acc[xx]);
            }
            #pragma unroll
            for (int xx = 0; xx < 4; xx++) Q[y * TX + x0 + xx] = acc[xx];
        } else {                                      // p12 stream: 21 row-pairs x 8 groups
            int v = u - 336;
            int y = (v / 8) * 2, x0 = (v % 8) * 4;
            const float* r0 = P12 + y * MWP + x0;
            const float* r1 = r0 + MWP;
            u64 w[14];
            #pragma unroll
            for (int j = 0; j < 14; j++) w[j] = pack2(r0[j], r1[j]);
            u64 acc[4] = {0ull, 0ull, 0ull, 0ull};
            #pragma unroll
            for (int k = 0; k < KS; k++) {
                #pragma unroll
                for (int xx = 0; xx < 4; xx++) acc[xx] = fma2(gg[k], w[xx + k], acc[xx]);
            }
            #pragma unroll
            for (int xx = 0; xx < 4; xx++) {
                float lo, hi;
                unpack2(acc[xx], lo, hi);
                Q12[y * TX + x0 + xx] = lo;
                Q12[(y + 1) * TX + x0 + xx] = hi;
            }
        }
    }
    __syncthreads();

    // ---- stage 5a: vertical conv of q -> SIG {sA,sB} and CC (c)  [32 x 32] ----
    for (int u = tid; u < 384; u += 256) {
        if (u < 256) {                                // pair stream: 32 cols x 8 groups
            int x = u % TX, y0 = (u / TX) * 4;
            u64 w[14];
            #pragma unroll
            for (int j = 0; j < 14; j++) w[j] = Q[(y0 + j) * TX + x];
            u64 acc[4] = {0ull, 0ull, 0ull, 0ull};
            #pragma unroll
            for (int k = 0; k < KS; k++) {
                #pragma unroll
                for (int yy = 0; yy < 4; yy++) acc[yy] = fma2(gg[k], w[yy + k], acc[yy]);
            }
            #pragma unroll
            for (int yy = 0; yy < 4; yy++) SIG[(y0 + yy) * TX + x] = acc[yy];
        } else {                                      // q12 stream: 16 col-pairs x 8 groups
            int v = u - 256;
            int xp = v % 16, y0 = (v / 16) * 4;
            const u64* qp = (const u64*)Q12;          // col-pair packed view
            u64 w[14];
            #pragma unroll
            for (int j = 0; j < 14; j++) w[j] = qp[(y0 + j) * (TX / 2) + xp];
            u64 acc[4] = {0ull, 0ull, 0ull, 0ull};
            #pragma unroll
            for (int k = 0; k < KS; k++) {
                #pragma unroll
                for (int yy = 0; yy < 4; yy++) acc[yy] = fma2(gg[k], w[yy + k], acc[yy]);
            }
            #pragma unroll
            for (int yy = 0; yy < 4; yy++) CCp[(y0 + yy) * (TX / 2) + xp] = acc[yy];
        }
    }
    __syncthreads();

    // ---- stage 5b: final SSIM math, accumulate (1 - ssim) ----
    float lsum = 0.f;
    #pragma unroll
    for (int it = 0; it < 4; it++) {
        int p = tid + it * 256;
        int y = p / TX, x = p % TX;
        float a, b, m1, m2;
        unpack2(SIG[y * TX + x], a, b);
        float c = CC[y * TX + x];
        unpack2(MU[(y + RAD) * MWP + (x + RAD)], m1, m2);
        float snum = 2.f * c + 2.f + C2;
        float sden = a + b + 2.f + C2;
        float m12  = m1 * m2 + 1.f;
        float t    = 2.f * m12;
        float msum = m1 * m1 + m2 * m2 + 2.f;
        float bnum = t * t + C1;
        float bden = msum * msum + C1;
        lsum += 1.f - __fdividef(snum * bnum, sden * bden);
    }

    // ---- block reduction + global accumulate ----
    #pragma unroll
    for (int o = 16; o; o >>= 1) lsum += __shfl_xor_sync(0xFFFFFFFFu, lsum, o);
    __shared__ float red[8];
    if ((tid & 31) == 0) red[tid >> 5] = lsum;
    __syncthreads();
    if (tid == 0) {
        float v = red[0];
        #pragma unroll
        for (int w = 1; w < 8; w++) v += red[w];
        atomicAdd(&g_accum, (double)v);
    }
}

// ---------------- kernel 4: finalize ----------------
__global__ void finalize_kernel(float* __restrict__ out) {
    out[0] = (float)(g_accum * (1.0 / NPIX));
}

// ---------------- launch ----------------
extern "C" void kernel_launch(void* const* d_in, const int* in_sizes, int n_in,
                              void* d_out, int out_size) {
    const float* img1 = (const float*)d_in[0];
    const float* img2 = (const float*)d_in[1];
    const float* k2d  = (const float*)d_in[2];
    float* out = (float*)d_out;

    init_kernel<<<1, 32>>>(k2d);

    int n4 = (NBAT * IMG_H * IMG_W) / 4;
    minmax_kernel<<<2048, 256>>>((const float4*)img1, (const float4*)img2, n4);

    cudaFuncSetAttribute(ssim_kernel, cudaFuncAttributeMaxDynamicSharedMemorySize, SMEM_BYTES);
    dim3 grid(IMG_W / TX, IMG_H / TY, NBAT);
    ssim_kernel<<<grid, 256, SMEM_BYTES>>>(img1, img2);

    finalize_kernel<<<1, 1>>>(out);
}

// round 3
// speedup vs baseline: 1.6063x; 1.2238x over previous
#include <cuda_runtime.h>

// ---------------- problem constants ----------------
#define KS    11
#define RAD   5
#define H2    10
#define TX    32
#define TY    32
#define IW    52          // TX + 2*H2 rows/cols of input tile
#define MW    42          // TX + 2*RAD
#define IMG_H 1024
#define IMG_W 1024
#define NBAT  16
#define NPIX  16777216.0

// row pitches chosen for bank-conflict-free access (u64 units)
#define ABP   58          // AB pitch  (≡2 mod 4: LDS.128 along-y conflict-free)
#define HP    46          // Hh/Pp pitch (≡2 mod 4)
#define MUP   45          // MU pitch (odd; accessed lanes-along-x only)
#define P12P  46          // P12 row-pair pitch (≡2 mod 4)
#define QP    33          // Q pitch (odd: STS.64 along-y conflict-free)

// smem layout in floats (all bases 16B aligned)
#define F_AB   0                         // u64[52][58] = 6032 f
#define F_H    6032                      // u64[52][46] = 4784 f  (reused as Pp[42][46])
#define F_MU   10816                     // u64[42][45] = 3780 f
#define F_P12  14596                     // u64[21][46] = 1932 f
#define SMEM_FLOATS 16528                // 66112 B
#define SMEM_BYTES  (SMEM_FLOATS * 4)
// aliases into AB region (used after AB is dead):
//   Q    u64[42][33] at F_AB          (2772 f)
//   Q12p u64[21][33] at F_AB + 2772   (1386 f)

typedef unsigned long long u64;

// ---------------- f32x2 helpers ----------------
__device__ __forceinline__ u64 pack2(float lo, float hi) {
    u64 r; asm("mov.b64 %0, {%1, %2};" : "=l"(r) : "f"(lo), "f"(hi)); return r;
}
__device__ __forceinline__ void unpack2(u64 v, float& lo, float& hi) {
    asm("mov.b64 {%0, %1}, %2;" : "=f"(lo), "=f"(hi) : "l"(v));
}
__device__ __forceinline__ u64 fma2(u64 a, u64 b, u64 c) {
    u64 d; asm("fma.rn.f32x2 %0, %1, %2, %3;" : "=l"(d) : "l"(a), "l"(b), "l"(c)); return d;
}
__device__ __forceinline__ u64 mul2(u64 a, u64 b) {
    u64 d; asm("mul.rn.f32x2 %0, %1, %2;" : "=l"(d) : "l"(a), "l"(b)); return d;
}

// ---------------- device globals ----------------
__device__ float        g_g1d[16];
__device__ unsigned int g_minkey;
__device__ unsigned int g_maxkey;
__device__ double       g_accum;

__device__ __forceinline__ unsigned int f2key(float f) {
    unsigned int u = __float_as_uint(f);
    return (u & 0x80000000u) ? ~u : (u | 0x80000000u);
}
__device__ __forceinline__ float key2f(unsigned int k) {
    unsigned int u = (k & 0x80000000u) ? (k & 0x7fffffffu) : ~k;
    return __uint_as_float(u);
}

// ---------------- kernel 1: init ----------------
__global__ void init_kernel(const float* __restrict__ k2d) {
    int t = threadIdx.x;
    if (t == 0) { g_accum = 0.0; g_minkey = 0xFFFFFFFFu; g_maxkey = 0u; }
    if (t < KS) {
        float s = 0.f;
        #pragma unroll
        for (int j = 0; j < KS; j++) s += k2d[t * KS + j];
        g_g1d[t] = s;
    }
}

// ---------------- kernel 2: global min/max ----------------
__global__ __launch_bounds__(256) void minmax_kernel(
    const float4* __restrict__ a, const float4* __restrict__ b, int n4)
{
    float mn = 1e30f, mx = -1e30f;
    int stride = gridDim.x * blockDim.x;
    for (int i = blockIdx.x * blockDim.x + threadIdx.x; i < n4; i += stride) {
        float4 v = a[i];
        float4 u = b[i];
        mn = fminf(mn, fminf(fminf(v.x, v.y), fminf(v.z, v.w)));
        mx = fmaxf(mx, fmaxf(fmaxf(v.x, v.y), fmaxf(v.z, v.w)));
        mn = fminf(mn, fminf(fminf(u.x, u.y), fminf(u.z, u.w)));
        mx = fmaxf(mx, fmaxf(fmaxf(u.x, u.y), fmaxf(u.z, u.w)));
    }
    #pragma unroll
    for (int o = 16; o; o >>= 1) {
        mn = fminf(mn, __shfl_xor_sync(0xFFFFFFFFu, mn, o));
        mx = fmaxf(mx, __shfl_xor_sync(0xFFFFFFFFu, mx, o));
    }
    __shared__ float smn[8], smx[8];
    int tid = threadIdx.x;
    if ((tid & 31) == 0) { smn[tid >> 5] = mn; smx[tid >> 5] = mx; }
    __syncthreads();
    if (tid == 0) {
        #pragma unroll
        for (int w = 1; w < 8; w++) { mn = fminf(mn, smn[w]); mx = fmaxf(mx, smx[w]); }
        atomicMin(&g_minkey, f2key(mn));
        atomicMax(&g_maxkey, f2key(mx));
    }
}

// ---------------- kernel 3: fused SSIM ----------------
__global__ __launch_bounds__(256, 3) void ssim_kernel(
    const float* __restrict__ img1, const float* __restrict__ img2)
{
    extern __shared__ float sm[];
    u64* AB   = (u64*)(sm + F_AB);
    u64* Hh   = (u64*)(sm + F_H);
    u64* MU   = (u64*)(sm + F_MU);
    u64* P12p = (u64*)(sm + F_P12);
    u64* Pp   = Hh;                         // alias (products, 42 rows)
    u64* Q    = (u64*)(sm + F_AB);          // alias after AB dead
    u64* Q12p = (u64*)(sm + F_AB + 2772);   // alias

    const int tid = threadIdx.x;
    const int ox = blockIdx.x * TX;
    const int oy = blockIdx.y * TY;
    const float* i1 = img1 + (size_t)blockIdx.z * (IMG_H * IMG_W);
    const float* i2 = img2 + (size_t)blockIdx.z * (IMG_H * IMG_W);

    float g[KS];
    u64 gg[KS];
    #pragma unroll
    for (int k = 0; k < KS; k++) { g[k] = g_g1d[k]; gg[k] = pack2(g[k], g[k]); }

    const float vr = key2f(g_maxkey) - key2f(g_minkey) + 1e-5f;
    float C1 = 0.01f * vr; C1 *= C1;
    float C2 = 0.03f * vr; C2 *= C2;

    // ---- load: interleave {img1,img2} into AB[52][58] (pads zeroed) ----
    for (int u = tid; u < IW * 29; u += 256) {
        int y = u / 29, c = 2 * (u % 29);
        int gy = oy - H2 + y, gx = ox - H2 + c;
        bool ok = (c < IW) && (gy >= 0) && (gy < IMG_H) && (gx >= 0) && (gx < IMG_W - 1);
        float2 va = make_float2(0.f, 0.f), vb = va;
        if (ok) {
            va = *(const float2*)(i1 + gy * IMG_W + gx);
            vb = *(const float2*)(i2 + gy * IMG_W + gx);
        }
        AB[y * ABP + c]     = pack2(va.x, vb.x);
        AB[y * ABP + c + 1] = pack2(va.y, vb.y);
    }
    __syncthreads();

    // ---- stage 1: horizontal conv -> Hh[52][46]  (lanes along y, LDS.128) ----
    for (int u = tid; u < IW * 11; u += 256) {       // 572 units
        int xg = u / IW, y = u % IW;
        int x0 = 4 * xg;
        const ulonglong2* r = (const ulonglong2*)(AB + y * ABP + x0);
        u64 w[14];
        #pragma unroll
        for (int j = 0; j < 7; j++) { ulonglong2 v = r[j]; w[2*j] = v.x; w[2*j+1] = v.y; }
        u64 acc[4] = {0ull, 0ull, 0ull, 0ull};
        #pragma unroll
        for (int k = 0; k < KS; k++) {
            #pragma unroll
            for (int xx = 0; xx < 4; xx++) acc[xx] = fma2(gg[k], w[xx + k], acc[xx]);
        }
        ulonglong2* o = (ulonglong2*)(Hh + y * HP + x0);
        o[0] = make_ulonglong2(acc[0], acc[1]);
        o[1] = make_ulonglong2(acc[2], acc[3]);
    }
    __syncthreads();

    // ---- stage 2: vertical conv -> MU[42][45]  (lanes along x) ----
    for (int u = tid; u < 11 * MW; u += 256) {       // 462 units
        int x = u % MW, y0 = (u / MW) * 4;
        u64 w[14];
        #pragma unroll
        for (int j = 0; j < 14; j++) {
            int yy = y0 + j;
            w[j] = (yy < IW) ? Hh[yy * HP + x] : 0ull;
        }
        u64 acc[4] = {0ull, 0ull, 0ull, 0ull};
        #pragma unroll
        for (int k = 0; k < KS; k++) {
            #pragma unroll
            for (int yy = 0; yy < 4; yy++) acc[yy] = fma2(gg[k], w[yy + k], acc[yy]);
        }
        #pragma unroll
        for (int yy = 0; yy < 4; yy++)
            if (y0 + yy < MW) MU[(y0 + yy) * MUP + x] = acc[yy];
    }
    __syncthreads();

    // ---- stage 3: deviations + products (2 rows per thread; packs p12 row-pairs) ----
    for (int i = tid; i < 21 * MW; i += 256) {       // 882 units
        int yp = i / MW, x = i % MW;
        int y0 = 2 * yp;
        float a0, b0, a1, b1, m0, n0, m1, n1;
        unpack2(AB[(y0 + RAD) * ABP + (x + RAD)], a0, b0);
        unpack2(AB[(y0 + RAD + 1) * ABP + (x + RAD)], a1, b1);
        unpack2(MU[y0 * MUP + x], m0, n0);
        unpack2(MU[(y0 + 1) * MUP + x], m1, n1);
        float d10 = a0 - m0, d20 = b0 - n0;
        float d11 = a1 - m1, d21 = b1 - n1;
        u64 dd0 = pack2(d10, d20);
        u64 dd1 = pack2(d11, d21);
        Pp[y0 * HP + x]       = mul2(dd0, dd0);
        Pp[(y0 + 1) * HP + x] = mul2(dd1, dd1);
        P12p[yp * P12P + x]   = pack2(d10 * d20, d11 * d21);
    }
    __syncthreads();

    // ---- stage 4: horizontal conv of products -> Q[42][33], Q12p[21][33] ----
    for (int u = tid; u < 504; u += 256) {
        if (u < 336) {                               // pair stream: 8 xg x 42 rows
            int xg = u / MW, y = u % MW;
            int x0 = 4 * xg;
            const ulonglong2* r = (const ulonglong2*)(Pp + y * HP + x0);
            u64 w[14];
            #pragma unroll
            for (int j = 0; j < 7; j++) { ulonglong2 v = r[j]; w[2*j] = v.x; w[2*j+1] = v.y; }
            u64 acc[4] = {0ull, 0ull, 0ull, 0ull};
            #pragma unroll
            for (int k = 0; k < KS; k++) {
                #pragma unroll
                for (int xx = 0; xx < 4; xx++) acc[xx] = fma2(gg[k], w[xx + k], acc[xx]);
            }
            #pragma unroll
            for (int xx = 0; xx < 4; xx++) Q[y * QP + x0 + xx] = acc[xx];
        } else {                                     // p12 row-pair stream: 8 xg x 21 pairs
            int v = u - 336;
            int xg = v / 21, yp = v % 21;
            int x0 = 4 * xg;
            const ulonglong2* r = (const ulonglong2*)(P12p + yp * P12P + x0);
            u64 w[14];
            #pragma unroll
            for (int j = 0; j < 7; j++) { ulonglong2 vv = r[j]; w[2*j] = vv.x; w[2*j+1] = vv.y; }
            u64 acc[4] = {0ull, 0ull, 0ull, 0ull};
            #pragma unroll
            for (int k = 0; k < KS; k++) {
                #pragma unroll
                for (int xx = 0; xx < 4; xx++) acc[xx] = fma2(gg[k], w[xx + k], acc[xx]);
            }
            #pragma unroll
            for (int xx = 0; xx < 4; xx++) Q12p[yp * QP + x0 + xx] = acc[xx];
        }
    }
    __syncthreads();

    // ---- stage 5: vertical conv of q + final SSIM math (exact 256 units) ----
    float lsum = 0.f;
    {
        int x = tid % TX, y0 = (tid / TX) * 4;       // y0 in {0,4,...,28}

        // q12 vertical (scalar): rows y0..y0+13 live in pairs y0/2 .. y0/2+6
        float accc[4] = {0.f, 0.f, 0.f, 0.f};
        {
            float cw[14];
            int yp0 = y0 >> 1;
            #pragma unroll
            for (int t = 0; t < 7; t++) {
                float lo, hi;
                unpack2(Q12p[(yp0 + t) * QP + x], lo, hi);
                cw[2*t] = lo; cw[2*t+1] = hi;
            }
            #pragma unroll
            for (int k = 0; k < KS; k++) {
                #pragma unroll
                for (int yy = 0; yy < 4; yy++) accc[yy] = fmaf(g[k], cw[yy + k], accc[yy]);
            }
        }

        // pair vertical
        u64 acc[4] = {0ull, 0ull, 0ull, 0ull};
        {
            u64 w[14];
            #pragma unroll
            for (int j = 0; j < 14; j++) w[j] = Q[(y0 + j) * QP + x];
            #pragma unroll
            for (int k = 0; k < KS; k++) {
                #pragma unroll
                for (int yy = 0; yy < 4; yy++) acc[yy] = fma2(gg[k], w[yy + k], acc[yy]);
            }
        }

        #pragma unroll
        for (int yy = 0; yy < 4; yy++) {
            int y = y0 + yy;
            float a, b, m1, m2;
            unpack2(acc[yy], a, b);
            unpack2(MU[(y + RAD) * MUP + (x + RAD)], m1, m2);
            float c = accc[yy];
            float snum = 2.f * c + 2.f + C2;
            float sden = a + b + 2.f + C2;
            float m12  = m1 * m2 + 1.f;
            float t    = 2.f * m12;
            float msum = m1 * m1 + m2 * m2 + 2.f;
            float bnum = t * t + C1;
            float bden = msum * msum + C1;
            lsum += 1.f - __fdividef(snum * bnum, sden * bden);
        }
    }

    // ---- block reduction + global accumulate ----
    #pragma unroll
    for (int o = 16; o; o >>= 1) lsum += __shfl_xor_sync(0xFFFFFFFFu, lsum, o);
    __shared__ float red[8];
    if ((tid & 31) == 0) red[tid >> 5] = lsum;
    __syncthreads();
    if (tid == 0) {
        float v = red[0];
        #pragma unroll
        for (int w = 1; w < 8; w++) v += red[w];
        atomicAdd(&g_accum, (double)v);
    }
}

// ---------------- kernel 4: finalize ----------------
__global__ void finalize_kernel(float* __restrict__ out) {
    out[0] = (float)(g_accum * (1.0 / NPIX));
}

// ---------------- launch ----------------
extern "C" void kernel_launch(void* const* d_in, const int* in_sizes, int n_in,
                              void* d_out, int out_size) {
    const float* img1 = (const float*)d_in[0];
    const float* img2 = (const float*)d_in[1];
    const float* k2d  = (const float*)d_in[2];
    float* out = (float*)d_out;

    init_kernel<<<1, 32>>>(k2d);

    int n4 = (NBAT * IMG_H * IMG_W) / 4;
    minmax_kernel<<<2048, 256>>>((const float4*)img1, (const float4*)img2, n4);

    cudaFuncSetAttribute(ssim_kernel, cudaFuncAttributeMaxDynamicSharedMemorySize, SMEM_BYTES);
    dim3 grid(IMG_W / TX, IMG_H / TY, NBAT);
    ssim_kernel<<<grid, 256, SMEM_BYTES>>>(img1, img2);

    finalize_kernel<<<1, 1>>>(out);
}

// round 4
// speedup vs baseline: 1.7790x; 1.1075x over previous
#include <cuda_runtime.h>

// ---------------- problem constants ----------------
#define KS    11
#define RAD   5
#define H2    10
#define TX    32
#define TY    32
#define IW    52          // TX + 2*H2
#define MW    42          // TX + 2*RAD
#define IMG_H 1024
#define IMG_W 1024
#define NBAT  16
#define NPIX  16777216.0

// pitches in u64 units, chosen conflict-free
#define ABP   58          // AB pitch   (29 ull2, odd -> LDS.128 along-y conflict-free)
#define HP    50          // Hh/Pp pitch (25 ull2, odd -> LDS.128 along-y conflict-free)
#define MUP   45          // MU pitch (lanes-along-x access only)
#define P12P  46          // P12p pitch (23 ull2, odd)
#define QP    33          // Q/Q12p pitch (odd -> LDS.64 along-y conflict-free)

// smem layout in floats (16B-aligned bases)
#define F_AB   0                         // u64[52][58] = 6032 f
#define F_H    6032                      // u64[52][50] = 5200 f (cols>=48 unused; reused as Pp[42][50])
#define F_MU   11232                     // u64[42][45] = 3780 f
#define F_P12  15012                     // u64[21][46] = 1932 f
#define SMEM_FLOATS 16944                // 67776 B
#define SMEM_BYTES  (SMEM_FLOATS * 4)
// aliases into AB region after AB is dead:
//   Q    u64[42][33] at F_AB          (1386 u64)
//   Q12p u64[21][33] at F_AB + 2772f  (693 u64)

typedef unsigned long long u64;

// ---------------- f32x2 helpers ----------------
__device__ __forceinline__ u64 pack2(float lo, float hi) {
    u64 r; asm("mov.b64 %0, {%1, %2};" : "=l"(r) : "f"(lo), "f"(hi)); return r;
}
__device__ __forceinline__ void unpack2(u64 v, float& lo, float& hi) {
    asm("mov.b64 {%0, %1}, %2;" : "=f"(lo), "=f"(hi) : "l"(v));
}
__device__ __forceinline__ u64 fma2(u64 a, u64 b, u64 c) {
    u64 d; asm("fma.rn.f32x2 %0, %1, %2, %3;" : "=l"(d) : "l"(a), "l"(b), "l"(c)); return d;
}
__device__ __forceinline__ u64 mul2(u64 a, u64 b) {
    u64 d; asm("mul.rn.f32x2 %0, %1, %2;" : "=l"(d) : "l"(a), "l"(b)); return d;
}

// ---------------- device globals ----------------
__device__ float        g_g1d[16];
__device__ unsigned int g_minkey;
__device__ unsigned int g_maxkey;
__device__ double       g_accum;

__device__ __forceinline__ unsigned int f2key(float f) {
    unsigned int u = __float_as_uint(f);
    return (u & 0x80000000u) ? ~u : (u | 0x80000000u);
}
__device__ __forceinline__ float key2f(unsigned int k) {
    unsigned int u = (k & 0x80000000u) ? (k & 0x7fffffffu) : ~k;
    return __uint_as_float(u);
}

// ---------------- kernel 1: init ----------------
__global__ void init_kernel(const float* __restrict__ k2d) {
    int t = threadIdx.x;
    if (t == 0) { g_accum = 0.0; g_minkey = 0xFFFFFFFFu; g_maxkey = 0u; }
    if (t < KS) {
        float s = 0.f;
        #pragma unroll
        for (int j = 0; j < KS; j++) s += k2d[t * KS + j];
        g_g1d[t] = s;
    }
}

// ---------------- kernel 2: global min/max ----------------
__global__ __launch_bounds__(256) void minmax_kernel(
    const float4* __restrict__ a, const float4* __restrict__ b, int n4)
{
    float mn = 1e30f, mx = -1e30f;
    int stride = gridDim.x * blockDim.x;
    for (int i = blockIdx.x * blockDim.x + threadIdx.x; i < n4; i += stride) {
        float4 v = a[i];
        float4 u = b[i];
        mn = fminf(mn, fminf(fminf(v.x, v.y), fminf(v.z, v.w)));
        mx = fmaxf(mx, fmaxf(fmaxf(v.x, v.y), fmaxf(v.z, v.w)));
        mn = fminf(mn, fminf(fminf(u.x, u.y), fminf(u.z, u.w)));
        mx = fmaxf(mx, fmaxf(fmaxf(u.x, u.y), fmaxf(u.z, u.w)));
    }
    #pragma unroll
    for (int o = 16; o; o >>= 1) {
        mn = fminf(mn, __shfl_xor_sync(0xFFFFFFFFu, mn, o));
        mx = fmaxf(mx, __shfl_xor_sync(0xFFFFFFFFu, mx, o));
    }
    __shared__ float smn[8], smx[8];
    int tid = threadIdx.x;
    if ((tid & 31) == 0) { smn[tid >> 5] = mn; smx[tid >> 5] = mx; }
    __syncthreads();
    if (tid == 0) {
        #pragma unroll
        for (int w = 1; w < 8; w++) { mn = fminf(mn, smn[w]); mx = fmaxf(mx, smx[w]); }
        atomicMin(&g_minkey, f2key(mn));
        atomicMax(&g_maxkey, f2key(mx));
    }
}

// ---------------- kernel 3: fused SSIM ----------------
__global__ __launch_bounds__(256, 3) void ssim_kernel(
    const float* __restrict__ img1, const float* __restrict__ img2)
{
    extern __shared__ float sm[];
    u64* AB   = (u64*)(sm + F_AB);
    u64* Hh   = (u64*)(sm + F_H);
    u64* MU   = (u64*)(sm + F_MU);
    u64* P12p = (u64*)(sm + F_P12);
    u64* Pp   = Hh;                         // alias (Hh dead after stage 2)
    u64* Q    = (u64*)(sm + F_AB);          // alias (AB dead after stage 3)
    u64* Q12p = (u64*)(sm + F_AB + 2772);

    const int tid = threadIdx.x;
    const int ox = blockIdx.x * TX;
    const int oy = blockIdx.y * TY;
    const float* i1 = img1 + (size_t)blockIdx.z * (IMG_H * IMG_W);
    const float* i2 = img2 + (size_t)blockIdx.z * (IMG_H * IMG_W);

    float g[KS];
    u64 gg[KS];
    #pragma unroll
    for (int k = 0; k < KS; k++) { g[k] = g_g1d[k]; gg[k] = pack2(g[k], g[k]); }

    const float vr = key2f(g_maxkey) - key2f(g_minkey) + 1e-5f;
    float C1 = 0.01f * vr; C1 *= C1;
    float C2 = 0.03f * vr; C2 *= C2;

    // ---- load: interleave {img1,img2} into AB[52][58] (pad cols zeroed) ----
    for (int u = tid; u < IW * 29; u += 256) {
        int y = u / 29, c = 2 * (u % 29);
        int gy = oy - H2 + y, gx = ox - H2 + c;
        bool ok = (c < IW) && (gy >= 0) && (gy < IMG_H) && (gx >= 0) && (gx < IMG_W - 1);
        float2 va = make_float2(0.f, 0.f), vb = va;
        if (ok) {
            va = *(const float2*)(i1 + gy * IMG_W + gx);
            vb = *(const float2*)(i2 + gy * IMG_W + gx);
        }
        AB[y * ABP + c]     = pack2(va.x, vb.x);
        AB[y * ABP + c + 1] = pack2(va.y, vb.y);
    }
    __syncthreads();

    // ---- stage 1: horizontal conv -> Hh[52 rows][48 cols used] ----
    // 312 units: 52 rows x 6 groups of 8 outputs (cols 42..47 are garbage, never read)
    for (int u = tid; u < IW * 6; u += 256) {
        int xg = u / IW, y = u % IW;
        int x0 = 8 * xg;                               // 0..40; window to x0+17 <= 57
        const ulonglong2* r = (const ulonglong2*)(AB + y * ABP + x0);
        u64 w[18];
        #pragma unroll
        for (int j = 0; j < 9; j++) { ulonglong2 v = r[j]; w[2*j] = v.x; w[2*j+1] = v.y; }
        u64 acc[8];
        #pragma unroll
        for (int xx = 0; xx < 8; xx++) acc[xx] = 0ull;
        #pragma unroll
        for (int k = 0; k < KS; k++) {
            #pragma unroll
            for (int xx = 0; xx < 8; xx++) acc[xx] = fma2(gg[k], w[xx + k], acc[xx]);
        }
        ulonglong2* o = (ulonglong2*)(Hh + y * HP + x0);
        #pragma unroll
        for (int xx = 0; xx < 4; xx++) o[xx] = make_ulonglong2(acc[2*xx], acc[2*xx+1]);
    }
    __syncthreads();

    // ---- stage 2: vertical conv -> MU[42][45] ----
    // 252 units: 6 row-groups of 7 x 42 cols (y0<=35 -> y0+16<=51: no guard)
    if (tid < 252) {
        int x = tid % MW, y0 = (tid / MW) * 7;
        u64 w[17];
        #pragma unroll
        for (int j = 0; j < 17; j++) w[j] = Hh[(y0 + j) * HP + x];
        u64 acc[7];
        #pragma unroll
        for (int yy = 0; yy < 7; yy++) acc[yy] = 0ull;
        #pragma unroll
        for (int k = 0; k < KS; k++) {
            #pragma unroll
            for (int yy = 0; yy < 7; yy++) acc[yy] = fma2(gg[k], w[yy + k], acc[yy]);
        }
        #pragma unroll
        for (int yy = 0; yy < 7; yy++) MU[(y0 + yy) * MUP + x] = acc[yy];
    }
    __syncthreads();

    // ---- stage 3: deviations + products (2 rows/thread; packs p12 row-pairs) ----
    for (int i = tid; i < 21 * MW; i += 256) {       // 882 units
        int yp = i / MW, x = i % MW;
        int y0 = 2 * yp;
        float a0, b0, a1, b1, m0, n0, m1, n1;
        unpack2(AB[(y0 + RAD) * ABP + (x + RAD)], a0, b0);
        unpack2(AB[(y0 + RAD + 1) * ABP + (x + RAD)], a1, b1);
        unpack2(MU[y0 * MUP + x], m0, n0);
        unpack2(MU[(y0 + 1) * MUP + x], m1, n1);
        float d10 = a0 - m0, d20 = b0 - n0;
        float d11 = a1 - m1, d21 = b1 - n1;
        u64 dd0 = pack2(d10, d20);
        u64 dd1 = pack2(d11, d21);
        Pp[y0 * HP + x]       = mul2(dd0, dd0);
        Pp[(y0 + 1) * HP + x] = mul2(dd1, dd1);
        P12p[yp * P12P + x]   = pack2(d10 * d20, d11 * d21);
    }
    __syncthreads();

    // ---- stage 4: horizontal conv of products -> Q[42][32], Q12p[21][32] ----
    // exactly 252 units: pair stream 42x4 + p12 stream 21x4, 8-wide groups
    if (tid < 252) {
        if (tid < 168) {
            int y = tid % MW, xg = tid / MW;
            int x0 = 8 * xg;                           // 0..24; window to x0+17 <= 41
            const ulonglong2* r = (const ulonglong2*)(Pp + y * HP + x0);
            u64 w[18];
            #pragma unroll
            for (int j = 0; j < 9; j++) { ulonglong2 v = r[j]; w[2*j] = v.x; w[2*j+1] = v.y; }
            u64 acc[8];
            #pragma unroll
            for (int xx = 0; xx < 8; xx++) acc[xx] = 0ull;
            #pragma unroll
            for (int k = 0; k < KS; k++) {
                #pragma unroll
                for (int xx = 0; xx < 8; xx++) acc[xx] = fma2(gg[k], w[xx + k], acc[xx]);
            }
            #pragma unroll
            for (int xx = 0; xx < 8; xx++) Q[y * QP + x0 + xx] = acc[xx];
        } else {
            int v = tid - 168;
            int yp = v % 21, xg = v / 21;
            int x0 = 8 * xg;
            const ulonglong2* r = (const ulonglong2*)(P12p + yp * P12P + x0);
            u64 w[18];
            #pragma unroll
            for (int j = 0; j < 9; j++) { ulonglong2 vv = r[j]; w[2*j] = vv.x; w[2*j+1] = vv.y; }
            u64 acc[8];
            #pragma unroll
            for (int xx = 0; xx < 8; xx++) acc[xx] = 0ull;
            #pragma unroll
            for (int k = 0; k < KS; k++) {
                #pragma unroll
                for (int xx = 0; xx < 8; xx++) acc[xx] = fma2(gg[k], w[xx + k], acc[xx]);
            }
            #pragma unroll
            for (int xx = 0; xx < 8; xx++) Q12p[yp * QP + x0 + xx] = acc[xx];
        }
    }
    __syncthreads();

    // ---- stage 5: vertical conv of q + final SSIM math (128 units, 8 rows each) ----
    float lsum = 0.f;
    if (tid < 128) {
        int x = tid % TX, y0 = (tid / TX) * 8;       // y0 in {0,8,16,24}

        // q12 vertical (scalar) first, to limit register peak
        float accc[8];
        #pragma unroll
        for (int yy = 0; yy < 8; yy++) accc[yy] = 0.f;
        {
            float cw[18];
            int yp0 = y0 >> 1;
            #pragma unroll
            for (int t = 0; t < 9; t++) {
                float lo, hi;
                unpack2(Q12p[(yp0 + t) * QP + x], lo, hi);
                cw[2*t] = lo; cw[2*t+1] = hi;
            }
            #pragma unroll
            for (int k = 0; k < KS; k++) {
                #pragma unroll
                for (int yy = 0; yy < 8; yy++) accc[yy] = fmaf(g[k], cw[yy + k], accc[yy]);
            }
        }

        // pair vertical
        u64 acc[8];
        #pragma unroll
        for (int yy = 0; yy < 8; yy++) acc[yy] = 0ull;
        {
            u64 w[18];
            #pragma unroll
            for (int j = 0; j < 18; j++) w[j] = Q[(y0 + j) * QP + x];
            #pragma unroll
            for (int k = 0; k < KS; k++) {
                #pragma unroll
                for (int yy = 0; yy < 8; yy++) acc[yy] = fma2(gg[k], w[yy + k], acc[yy]);
            }
        }

        #pragma unroll
        for (int yy = 0; yy < 8; yy++) {
            int y = y0 + yy;
            float a, b, m1, m2;
            unpack2(acc[yy], a, b);
            unpack2(MU[(y + RAD) * MUP + (x + RAD)], m1, m2);
            float c = accc[yy];
            float snum = 2.f * c + 2.f + C2;
            float sden = a + b + 2.f + C2;
            float m12  = m1 * m2 + 1.f;
            float t    = 2.f * m12;
            float msum = m1 * m1 + m2 * m2 + 2.f;
            float bnum = t * t + C1;
            float bden = msum * msum + C1;
            lsum += 1.f - __fdividef(snum * bnum, sden * bden);
        }
    }

    // ---- block reduction + global accumulate ----
    #pragma unroll
    for (int o = 16; o; o >>= 1) lsum += __shfl_xor_sync(0xFFFFFFFFu, lsum, o);
    __shared__ float red[8];
    if ((tid & 31) == 0) red[tid >> 5] = lsum;
    __syncthreads();
    if (tid == 0) {
        float v = red[0] + red[1] + red[2] + red[3];
        atomicAdd(&g_accum, (double)v);
    }
}

// ---------------- kernel 4: finalize ----------------
__global__ void finalize_kernel(float* __restrict__ out) {
    out[0] = (float)(g_accum * (1.0 / NPIX));
}

// ---------------- launch ----------------
extern "C" void kernel_launch(void* const* d_in, const int* in_sizes, int n_in,
                              void* d_out, int out_size) {
    const float* img1 = (const float*)d_in[0];
    const float* img2 = (const float*)d_in[1];
    const float* k2d  = (const float*)d_in[2];
    float* out = (float*)d_out;

    init_kernel<<<1, 32>>>(k2d);

    int n4 = (NBAT * IMG_H * IMG_W) / 4;
    minmax_kernel<<<2048, 256>>>((const float4*)img1, (const float4*)img2, n4);

    cudaFuncSetAttribute(ssim_kernel, cudaFuncAttributeMaxDynamicSharedMemorySize, SMEM_BYTES);
    dim3 grid(IMG_W / TX, IMG_H / TY, NBAT);
    ssim_kernel<<<grid, 256, SMEM_BYTES>>>(img1, img2);

    finalize_kernel<<<1, 1>>>(out);
}

// round 5
// speedup vs baseline: 1.8116x; 1.0183x over previous
#include <cuda_runtime.h>

// ---------------- problem constants ----------------
#define KS    11
#define RAD   5
#define H2    10
#define TX    32
#define TY    32
#define IW    52          // TX + 2*H2
#define MW    42          // TX + 2*RAD
#define IMG_H 1024
#define IMG_W 1024
#define NBAT  16
#define NPIX  16777216.0

// pitches (u64 units), conflict-free for their access patterns:
#define ABP   59          // odd -> LDS.64 lanes-along-y conflict-free
#define HP    50          // 100 words: STS.128/LDS.128 lanes-along-y conflict-free
#define MUP   45          // odd -> LDS.64 lanes-along-y conflict-free
#define QP    33          // odd -> STS.64 lanes-along-y conflict-free
#define Q12P  33          // floats

// smem layout in floats (16B-aligned bases)
#define F_AB   0                         // u64[52][59] = 6136 f
#define F_H    6136                      // u64[52][50] = 5200 f (cols>=48 garbage)
#define F_MU   11336                     // u64[42][45] = 3780 f (stores NEGATED mu)
#define SMEM_FLOATS 15116                // 60464 B
#define SMEM_BYTES  (SMEM_FLOATS * 4)
// aliases into H region after stage 2 (H dead):
//   Q    u64 [42][33] at F_H            (2772 f)
//   Q12f float[42][33] at F_H + 2772    (1386 f)

typedef unsigned long long u64;

// ---------------- f32x2 helpers ----------------
__device__ __forceinline__ u64 pack2(float lo, float hi) {
    u64 r; asm("mov.b64 %0, {%1, %2};" : "=l"(r) : "f"(lo), "f"(hi)); return r;
}
__device__ __forceinline__ void unpack2(u64 v, float& lo, float& hi) {
    asm("mov.b64 {%0, %1}, %2;" : "=f"(lo), "=f"(hi) : "l"(v));
}
__device__ __forceinline__ u64 fma2(u64 a, u64 b, u64 c) {
    u64 d; asm("fma.rn.f32x2 %0, %1, %2, %3;" : "=l"(d) : "l"(a), "l"(b), "l"(c)); return d;
}
__device__ __forceinline__ u64 mul2(u64 a, u64 b) {
    u64 d; asm("mul.rn.f32x2 %0, %1, %2;" : "=l"(d) : "l"(a), "l"(b)); return d;
}
__device__ __forceinline__ u64 add2(u64 a, u64 b) {
    u64 d; asm("add.rn.f32x2 %0, %1, %2;" : "=l"(d) : "l"(a), "l"(b)); return d;
}

// ---------------- device globals ----------------
__device__ float        g_g1d[16];
__device__ unsigned int g_minkey;
__device__ unsigned int g_maxkey;
__device__ double       g_accum;

__device__ __forceinline__ unsigned int f2key(float f) {
    unsigned int u = __float_as_uint(f);
    return (u & 0x80000000u) ? ~u : (u | 0x80000000u);
}
__device__ __forceinline__ float key2f(unsigned int k) {
    unsigned int u = (k & 0x80000000u) ? (k & 0x7fffffffu) : ~k;
    return __uint_as_float(u);
}

// ---------------- kernel 1: init ----------------
__global__ void init_kernel(const float* __restrict__ k2d) {
    int t = threadIdx.x;
    if (t == 0) { g_accum = 0.0; g_minkey = 0xFFFFFFFFu; g_maxkey = 0u; }
    if (t < KS) {
        float s = 0.f;
        #pragma unroll
        for (int j = 0; j < KS; j++) s += k2d[t * KS + j];
        g_g1d[t] = s;
    }
}

// ---------------- kernel 2: global min/max ----------------
__global__ __launch_bounds__(256) void minmax_kernel(
    const float4* __restrict__ a, const float4* __restrict__ b, int n4)
{
    float mn = 1e30f, mx = -1e30f;
    int stride = gridDim.x * blockDim.x;
    for (int i = blockIdx.x * blockDim.x + threadIdx.x; i < n4; i += stride) {
        float4 v = a[i];
        float4 u = b[i];
        mn = fminf(mn, fminf(fminf(v.x, v.y), fminf(v.z, v.w)));
        mx = fmaxf(mx, fmaxf(fmaxf(v.x, v.y), fmaxf(v.z, v.w)));
        mn = fminf(mn, fminf(fminf(u.x, u.y), fminf(u.z, u.w)));
        mx = fmaxf(mx, fmaxf(fmaxf(u.x, u.y), fmaxf(u.z, u.w)));
    }
    #pragma unroll
    for (int o = 16; o; o >>= 1) {
        mn = fminf(mn, __shfl_xor_sync(0xFFFFFFFFu, mn, o));
        mx = fmaxf(mx, __shfl_xor_sync(0xFFFFFFFFu, mx, o));
    }
    __shared__ float smn[8], smx[8];
    int tid = threadIdx.x;
    if ((tid & 31) == 0) { smn[tid >> 5] = mn; smx[tid >> 5] = mx; }
    __syncthreads();
    if (tid == 0) {
        #pragma unroll
        for (int w = 1; w < 8; w++) { mn = fminf(mn, smn[w]); mx = fmaxf(mx, smx[w]); }
        atomicMin(&g_minkey, f2key(mn));
        atomicMax(&g_maxkey, f2key(mx));
    }
}

// ---------------- kernel 3: fused SSIM ----------------
__global__ __launch_bounds__(256, 3) void ssim_kernel(
    const float* __restrict__ img1, const float* __restrict__ img2)
{
    extern __shared__ float sm[];
    u64*   AB   = (u64*)(sm + F_AB);
    u64*   Hh   = (u64*)(sm + F_H);
    u64*   MU   = (u64*)(sm + F_MU);          // holds NEGATED mu
    u64*   Q    = (u64*)(sm + F_H);           // alias (H dead after stage 2)
    float* Q12f = sm + F_H + 2772;

    const int tid = threadIdx.x;
    const int ox = blockIdx.x * TX;
    const int oy = blockIdx.y * TY;
    const float* i1 = img1 + (size_t)blockIdx.z * (IMG_H * IMG_W);
    const float* i2 = img2 + (size_t)blockIdx.z * (IMG_H * IMG_W);

    float g[KS];
    u64 gg[KS];
    #pragma unroll
    for (int k = 0; k < KS; k++) { g[k] = g_g1d[k]; gg[k] = pack2(g[k], g[k]); }

    const float vr = key2f(g_maxkey) - key2f(g_minkey) + 1e-5f;
    float C1 = 0.01f * vr; C1 *= C1;
    float C2 = 0.03f * vr; C2 *= C2;

    // ---- load: interleave {img1,img2} into AB[52][59] (cols 52..57 zeroed) ----
    for (int u = tid; u < IW * 29; u += 256) {
        int y = u / 29, c = 2 * (u % 29);            // c in {0,...,56}
        int gy = oy - H2 + y, gx = ox - H2 + c;
        bool ok = (c < IW) && (gy >= 0) && (gy < IMG_H) && (gx >= 0) && (gx < IMG_W - 1);
        float2 va = make_float2(0.f, 0.f), vb = va;
        if (ok) {
            va = *(const float2*)(i1 + gy * IMG_W + gx);
            vb = *(const float2*)(i2 + gy * IMG_W + gx);
        }
        AB[y * ABP + c] = pack2(va.x, vb.x);
        if (c + 1 <= 57) AB[y * ABP + c + 1] = pack2(va.y, vb.y);
    }
    __syncthreads();

    // ---- stage 1: horizontal conv -> Hh[52 rows][48 cols, 42 used] ----
    // 312 units (52 rows x 6 groups of 8), streaming window
    for (int u = tid; u < IW * 6; u += 256) {
        int xg = u / IW, y = u % IW;                 // lanes along y
        int x0 = 8 * xg;                             // 0..40; reads to col 57
        const u64* r = AB + y * ABP + x0;
        u64 acc[8];
        #pragma unroll
        for (int xx = 0; xx < 8; xx++) acc[xx] = 0ull;
        #pragma unroll
        for (int j = 0; j < 18; j++) {
            u64 w = r[j];
            #pragma unroll
            for (int xx = 0; xx < 8; xx++)
                if (xx <= j && j - xx <= 10) acc[xx] = fma2(gg[j - xx], w, acc[xx]);
        }
        ulonglong2* o = (ulonglong2*)(Hh + y * HP + x0);
        #pragma unroll
        for (int xx = 0; xx < 4; xx++) o[xx] = make_ulonglong2(acc[2*xx], acc[2*xx+1]);
    }
    __syncthreads();

    // ---- stage 2: vertical conv -> -MU[42][45]  (252 units, 7 rows each) ----
    if (tid < 252) {
        int x = tid % MW, y0 = (tid / MW) * 7;       // lanes along x
        u64 acc[7];
        #pragma unroll
        for (int yy = 0; yy < 7; yy++) acc[yy] = 0ull;
        #pragma unroll
        for (int j = 0; j < 17; j++) {
            u64 w = Hh[(y0 + j) * HP + x];
            #pragma unroll
            for (int yy = 0; yy < 7; yy++)
                if (yy <= j && j - yy <= 10) acc[yy] = fma2(gg[j - yy], w, acc[yy]);
        }
        #pragma unroll
        for (int yy = 0; yy < 7; yy++)
            MU[(y0 + yy) * MUP + x] = acc[yy] ^ 0x8000000080000000ULL;  // store -mu
    }
    __syncthreads();

    // ---- stage 4': products on the fly + horizontal conv -> Q{q1,q2}, Q12f ----
    // 168 units: 42 rows x 4 groups of 8 outputs (writes alias H: barrier above)
    if (tid < 168) {
        int y = tid % MW, xg = tid / MW;             // lanes along y
        int x0 = 8 * xg;                             // 0..24
        const u64* ar = AB + (y + RAD) * ABP + (x0 + RAD);
        const u64* mr = MU + y * MUP + x0;
        u64 accq[8];
        float accc[8];
        #pragma unroll
        for (int xx = 0; xx < 8; xx++) { accq[xx] = 0ull; accc[xx] = 0.f; }
        #pragma unroll
        for (int j = 0; j < 18; j++) {
            u64 dd = add2(ar[j], mr[j]);             // a - mu (MU negated)
            u64 pp = mul2(dd, dd);                   // {d1^2, d2^2}
            float d1, d2;
            unpack2(dd, d1, d2);
            float cv = d1 * d2;
            #pragma unroll
            for (int xx = 0; xx < 8; xx++)
                if (xx <= j && j - xx <= 10) {
                    accq[xx] = fma2(gg[j - xx], pp, accq[xx]);
                    accc[xx] = fmaf(g[j - xx], cv, accc[xx]);
                }
        }
        #pragma unroll
        for (int xx = 0; xx < 8; xx++) {
            Q[y * QP + x0 + xx]      = accq[xx];
            Q12f[y * Q12P + x0 + xx] = accc[xx];
        }
    }
    __syncthreads();

    // ---- stage 5: vertical conv of q + final SSIM math (128 units, 8 rows) ----
    float lsum = 0.f;
    if (tid < 128) {
        int x = tid % TX, y0 = (tid / TX) * 8;       // lanes along x
        u64 accq[8];
        float accc[8];
        #pragma unroll
        for (int yy = 0; yy < 8; yy++) { accq[yy] = 0ull; accc[yy] = 0.f; }
        #pragma unroll
        for (int j = 0; j < 18; j++) {
            u64 qv   = Q[(y0 + j) * QP + x];
            float cv = Q12f[(y0 + j) * Q12P + x];
            #pragma unroll
            for (int yy = 0; yy < 8; yy++)
                if (yy <= j && j - yy <= 10) {
                    accq[yy] = fma2(gg[j - yy], qv, accq[yy]);
                    accc[yy] = fmaf(g[j - yy], cv, accc[yy]);
                }
        }
        #pragma unroll
        for (int yy = 0; yy < 8; yy++) {
            int y = y0 + yy;
            float a, b, m1, m2;
            unpack2(accq[yy], a, b);
            unpack2(MU[(y + RAD) * MUP + (x + RAD)], m1, m2);   // negated: even terms only
            float c = accc[yy];
            float snum = 2.f * c + 2.f + C2;
            float sden = a + b + 2.f + C2;
            float m12  = m1 * m2 + 1.f;                          // (-m1)(-m2) = m1 m2
            float t    = 2.f * m12;
            float msum = m1 * m1 + m2 * m2 + 2.f;
            float bnum = t * t + C1;
            float bden = msum * msum + C1;
            lsum += 1.f - __fdividef(snum * bnum, sden * bden);
        }
    }

    // ---- block reduction + global accumulate ----
    #pragma unroll
    for (int o = 16; o; o >>= 1) lsum += __shfl_xor_sync(0xFFFFFFFFu, lsum, o);
    __shared__ float red[8];
    if ((tid & 31) == 0) red[tid >> 5] = lsum;
    __syncthreads();
    if (tid == 0) {
        float v = red[0] + red[1] + red[2] + red[3];
        atomicAdd(&g_accum, (double)v);
    }
}

// ---------------- kernel 4: finalize ----------------
__global__ void finalize_kernel(float* __restrict__ out) {
    out[0] = (float)(g_accum * (1.0 / NPIX));
}

// ---------------- launch ----------------
extern "C" void kernel_launch(void* const* d_in, const int* in_sizes, int n_in,
                              void* d_out, int out_size) {
    const float* img1 = (const float*)d_in[0];
    const float* img2 = (const float*)d_in[1];
    const float* k2d  = (const float*)d_in[2];
    float* out = (float*)d_out;

    init_kernel<<<1, 32>>>(k2d);

    int n4 = (NBAT * IMG_H * IMG_W) / 4;
    minmax_kernel<<<2048, 256>>>((const float4*)img1, (const float4*)img2, n4);

    cudaFuncSetAttribute(ssim_kernel, cudaFuncAttributeMaxDynamicSharedMemorySize, SMEM_BYTES);
    dim3 grid(IMG_W / TX, IMG_H / TY, NBAT);
    ssim_kernel<<<grid, 256, SMEM_BYTES>>>(img1, img2);

    finalize_kernel<<<1, 1>>>(out);
}